// round 4
// baseline (speedup 1.0000x reference)
#include <cuda_runtime.h>

#define NXc 64
#define NYc 64
#define NSPOTS 64
#define PATCH_HW 3
#define Pc 6
#define TPB 256          // 8 warps; warp w owns image rows [8w, 8w+8)

__global__ __launch_bounds__(TPB) void spot_render_kernel(
    const float* __restrict__ z, float* __restrict__ out)
{
    __shared__ float slx[NSPOTS * Pc];   // I0 * lam_x * valid
    __shared__ float sly[NSPOTS * Pc];   // lam_y * valid
    __shared__ int   spxy[NSPOTS];       // clamped row0(px) | col0(py)<<8
    __shared__ float sx0p[NSPOTS];
    __shared__ float sy0p[NSPOTS];
    __shared__ float sval[NSPOTS];
    __shared__ unsigned char slist[8][NSPOTS];

    const int b       = blockIdx.x;
    const int tid     = threadIdx.x;
    const int lane    = tid & 31;
    const int w       = tid >> 5;
    const int band_lo = w << 3;

    const float inv_alpha = 0.76870611479f;  // 1/(sqrt(2)*0.92)

    // ---- per-spot meta ----
    if (tid < NSPOTS) {
        const int s = tid;
        const float* zrow = z + (size_t)b * (2 * NSPOTS);
        const float x0 = __ldg(zrow + s);
        const float y0 = __ldg(zrow + NSPOTS + s);
        const int px = __float2int_rn(x0) - PATCH_HW;   // round-half-even == jnp.round
        const int py = __float2int_rn(y0) - PATCH_HW;
        const bool valid = (px >= 0) & (px < NXc - Pc) & (py >= 0) & (py < NYc - Pc);
        spxy[s] = (valid ? px : 0) | ((valid ? py : 0) << 8);
        sx0p[s] = x0 - (float)px;
        sy0p[s] = y0 - (float)py;
        sval[s] = valid ? 1.0f : 0.0f;
    }
    __syncthreads();

    // ---- build this warp's spot list (ascending s -> deterministic) ----
    int cnt;
    {
        const int r0a = spxy[lane] & 255;
        const bool ova = (r0a + Pc > band_lo) && (r0a < band_lo + 8);
        const unsigned m0 = __ballot_sync(0xFFFFFFFFu, ova);
        const int r0b = spxy[lane + 32] & 255;
        const bool ovb = (r0b + Pc > band_lo) && (r0b < band_lo + 8);
        const unsigned m1 = __ballot_sync(0xFFFFFFFFu, ovb);
        const unsigned below = (1u << lane) - 1u;
        if (ova) slist[w][__popc(m0 & below)] = (unsigned char)lane;
        const int base = __popc(m0);
        if (ovb) slist[w][base + __popc(m1 & below)] = (unsigned char)(32 + lane);
        cnt = base + __popc(m1);
    }

    // ---- phase B: 768 lambda values (exact reference arg form) ----
    #pragma unroll
    for (int k = 0; k < 3; k++) {
        const int i  = k * TPB + tid;
        const int s  = i & 63;
        const int jj = i >> 6;
        const bool isx = (jj < Pc);
        const float t  = (float)(isx ? jj : jj - Pc);
        const float t0 = isx ? sx0p[s] : sy0p[s];
        float lam = 0.5f * (erff((t + 0.5f - t0) * inv_alpha) -
                            erff((t - 0.5f - t0) * inv_alpha));
        lam *= sval[s];
        if (isx) slx[s * Pc + jj]        = lam * 1000.0f;   // fold I0
        else     sly[s * Pc + (jj - Pc)] = lam;
    }
    __syncthreads();   // also orders slist writes for the consuming warp

    // ---- phase C: register-tile accumulation, no atomics ----
    // lane owns columns c0 = 2*lane and c0+1 across the warp's 8 rows
    float acc[8][2];
    #pragma unroll
    for (int r = 0; r < 8; r++) { acc[r][0] = 0.0f; acc[r][1] = 0.0f; }

    const int c0 = lane << 1;
    for (int k = 0; k < cnt; k++) {
        const int s    = slist[w][k];         // warp-uniform broadcast
        const int meta = spxy[s];
        const int row0 = meta & 255;
        const int col0 = meta >> 8;
        const int iy0  = c0 - col0;
        const float ly0 = ((unsigned)iy0 < 6u)       ? sly[s * Pc + iy0]     : 0.0f;
        const float ly1 = ((unsigned)(iy0 + 1) < 6u) ? sly[s * Pc + iy0 + 1] : 0.0f;
        const float* lxp = &slx[s * Pc];
        #pragma unroll
        for (int r = 0; r < 8; r++) {
            const int ix = band_lo + r - row0;            // warp-uniform
            const float lx = ((unsigned)ix < 6u) ? lxp[ix] : 0.0f;
            acc[r][0] = fmaf(lx, ly0, acc[r][0]);
            acc[r][1] = fmaf(lx, ly1, acc[r][1]);
        }
    }

    // ---- writeback: direct float2 stores from registers ----
    float2* orow = reinterpret_cast<float2*>(out + (size_t)b * (NXc * NYc));
    #pragma unroll
    for (int r = 0; r < 8; r++) {
        orow[(band_lo + r) * (NYc / 2) + lane] = make_float2(acc[r][0], acc[r][1]);
    }
}

extern "C" void kernel_launch(void* const* d_in, const int* in_sizes, int n_in,
                              void* d_out, int out_size)
{
    const float* z = (const float*)d_in[0];
    float* out = (float*)d_out;
    const int B = in_sizes[0] / (2 * NSPOTS);   // 8192
    spot_render_kernel<<<B, TPB>>>(z, out);
}

// round 5
// speedup vs baseline: 1.8749x; 1.8749x over previous
#include <cuda_runtime.h>

#define NXc 64
#define NYc 64
#define NSPOTS 64
#define PATCH_HW 3
#define Pc 6
#define TPB 256

__global__ __launch_bounds__(TPB) void spot_render_kernel(
    const float* __restrict__ z, float* __restrict__ out)
{
    __shared__ float img[NXc * NYc];     // 16 KB, rotate-6 swizzled rows
    __shared__ float slx[NSPOTS * Pc];   // I0 * lam_x * valid
    __shared__ float sly[NSPOTS * Pc];   // lam_y * valid
    __shared__ int   spxy[NSPOTS];       // clamped px | py<<8
    __shared__ float sx0p[NSPOTS];
    __shared__ float sy0p[NSPOTS];
    __shared__ float sval[NSPOTS];

    const int b    = blockIdx.x;
    const int tid  = threadIdx.x;
    const int lane = tid & 31;
    const int w    = tid >> 5;

    const float inv_alpha = 1.0f / (1.41421356237f * 0.92f);  // 0.768594...

    // ---- prologue: zero image (float4), per-spot meta ----
    {
        float4* im4 = reinterpret_cast<float4*>(img);
        #pragma unroll
        for (int i = tid; i < (NXc * NYc) / 4; i += TPB)
            im4[i] = make_float4(0.f, 0.f, 0.f, 0.f);
    }
    if (tid < NSPOTS) {
        const int s = tid;
        const float* zrow = z + (size_t)b * (2 * NSPOTS);
        const float x0 = __ldg(zrow + s);
        const float y0 = __ldg(zrow + NSPOTS + s);
        const int px = __float2int_rn(x0) - PATCH_HW;   // round-half-even == jnp.round
        const int py = __float2int_rn(y0) - PATCH_HW;
        const bool valid = (px >= 0) & (px < NXc - Pc) & (py >= 0) & (py < NYc - Pc);
        spxy[s] = (valid ? px : 0) | ((valid ? py : 0) << 8);
        sx0p[s] = x0 - (float)px;
        sy0p[s] = y0 - (float)py;
        sval[s] = valid ? 1.0f : 0.0f;
    }
    __syncthreads();

    // ---- phase B: 768 lambda values ----
    #pragma unroll
    for (int k = 0; k < 3; k++) {
        const int i  = k * TPB + tid;
        const int s  = i & 63;
        const int jj = i >> 6;
        const bool isx = (jj < Pc);
        const float t  = (float)(isx ? jj : jj - Pc);
        const float t0 = isx ? sx0p[s] : sy0p[s];
        float lam = 0.5f * (erff((t + 0.5f - t0) * inv_alpha) -
                            erff((t - 0.5f - t0) * inv_alpha));
        lam *= sval[s];
        if (isx) slx[s * Pc + jj]        = lam * 1000.0f;   // fold I0
        else     sly[s * Pc + (jj - Pc)] = lam;
    }
    __syncthreads();

    // ---- phase C: warp-per-spot scatter, conflict-free atomics ----
    // pixel index p = 6*ix + iy; swizzled addr = (r0+ix)*64 + ((c0+6*r0 + p) & 63)
    // -> bank = (K + p) mod 32, p = 0..31 distinct -> zero bank conflicts
    const int p  = lane;
    const int ix = (p * 171) >> 10;          // p/6 for p <= 35
    const int iy = p - ix * Pc;
    #pragma unroll
    for (int k = 0; k < 8; k++) {
        const int s    = w * 8 + k;
        const int meta = spxy[s];            // broadcast
        const int r0   = meta & 255;
        const int c0   = meta >> 8;
        const int K    = (c0 + 6 * r0) & 63;
        const float v  = slx[s * Pc + ix] * sly[s * Pc + iy];
        atomicAdd(&img[((r0 + ix) << 6) + ((K + p) & 63)], v);
    }
    // batched residuals: pixels p'=32..35 (ix=5, iy=2..5) of all 8 spots in ONE atomic
    {
        const int s2   = w * 8 + (lane >> 2);
        const int p2   = 32 + (lane & 3);    // = 6*5 + iy, iy = 2+(lane&3)
        const int meta = spxy[s2];
        const int r0   = meta & 255;
        const int c0   = meta >> 8;
        const int K    = (c0 + 6 * r0) & 63;
        const float v  = slx[s2 * Pc + 5] * sly[s2 * Pc + (p2 - 30)];
        atomicAdd(&img[((r0 + 5) << 6) + ((K + p2) & 63)], v);
    }
    __syncthreads();

    // ---- phase D: un-swizzle + coalesced float2 writeback ----
    // out float2 (r, cg)  <-  img float2 idx (r<<5) + ((cg + 3r) & 31)
    float2* o2 = reinterpret_cast<float2*>(out + (size_t)b * (NXc * NYc));
    const float2* im2 = reinterpret_cast<const float2*>(img);
    #pragma unroll
    for (int k = 0; k < 8; k++) {
        const int i  = k * TPB + tid;
        const int r  = i >> 5;               // warp-uniform
        const int cg = i & 31;
        o2[i] = im2[(r << 5) + ((cg + 3 * r) & 31)];
    }
}

extern "C" void kernel_launch(void* const* d_in, const int* in_sizes, int n_in,
                              void* d_out, int out_size)
{
    const float* z = (const float*)d_in[0];
    float* out = (float*)d_out;
    const int B = in_sizes[0] / (2 * NSPOTS);   // 8192
    spot_render_kernel<<<B, TPB>>>(z, out);
}